// round 15
// baseline (speedup 1.0000x reference)
#include <cuda_runtime.h>
#include <cuda_fp16.h>
#include <cstdint>
#include <cstddef>

#define T_TOK 8192
#define NJ    24
#define NH    8
#define FD    32
#define JD    6144
#define OUTJ  768

__device__ __half g_Qh[(size_t)T_TOK * JD];        // q fp16 [t][h][n][f]
__device__ __half g_Kh[(size_t)T_TOK * JD];        // k fp16
__device__ __half g_Vh[(size_t)T_TOK * JD];        // v fp16
__device__ __half g_xh[(size_t)T_TOK * JD];        // x fp16
__device__ __half g_Wh[(size_t)NJ * OUTJ * 256];   // [n][j][d] fp16
__device__ float  g_bias[NJ * OUTJ];

__device__ __forceinline__ uint32_t smem_u32(const void* p) {
    uint32_t a;
    asm("{ .reg .u64 t; cvta.to.shared.u64 t, %1; cvt.u32.u64 %0, t; }" : "=r"(a) : "l"(p));
    return a;
}
__device__ __forceinline__ void mma_f16(float* d, const unsigned* a, unsigned b0, unsigned b1) {
    asm volatile(
        "mma.sync.aligned.m16n8k16.row.col.f32.f16.f16.f32 "
        "{%0,%1,%2,%3}, {%4,%5,%6,%7}, {%8,%9}, {%0,%1,%2,%3};\n"
        : "+f"(d[0]), "+f"(d[1]), "+f"(d[2]), "+f"(d[3])
        : "r"(a[0]), "r"(a[1]), "r"(a[2]), "r"(a[3]), "r"(b0), "r"(b1));
}
__device__ __forceinline__ void cp16(uint32_t d, const void* s) {
    asm volatile("cp.async.cg.shared.global [%0], [%1], 16;" :: "r"(d), "l"(s));
}
#define CPC()  asm volatile("cp.async.commit_group;" ::: "memory")
#define CPW(n) asm volatile("cp.async.wait_group %0;" :: "n"(n) : "memory")

// ------------------------------- prep ---------------------------------------
__global__ void prep_x_kernel(const float* __restrict__ x) {
    size_t i = (size_t)blockIdx.x * blockDim.x + threadIdx.x;
    const size_t total8 = (size_t)T_TOK * JD / 8;
    if (i < total8) {
        float4 v0 = ((const float4*)x)[2 * i];
        float4 v1 = ((const float4*)x)[2 * i + 1];
        __half2 h0 = __floats2half2_rn(v0.x, v0.y);
        __half2 h1 = __floats2half2_rn(v0.z, v0.w);
        __half2 h2 = __floats2half2_rn(v1.x, v1.y);
        __half2 h3 = __floats2half2_rn(v1.z, v1.w);
        uint4 o;
        o.x = *(uint32_t*)&h0; o.y = *(uint32_t*)&h1;
        o.z = *(uint32_t*)&h2; o.w = *(uint32_t*)&h3;
        ((uint4*)g_xh)[i] = o;
    }
}
__global__ void prep_w_kernel(const float* __restrict__ Wq, const float* __restrict__ Wk,
                              const float* __restrict__ Wv) {
    const size_t total = (size_t)NJ * OUTJ * 256;
    for (size_t i = (size_t)blockIdx.x * blockDim.x + threadIdx.x; i < total;
         i += (size_t)gridDim.x * blockDim.x) {
        int d = (int)(i & 255);
        size_t nj = i >> 8;
        int j = (int)(nj % OUTJ), n = (int)(nj / OUTJ);
        int h = (j >> 5) & 7, f = j & 31;
        float v;
        if (j < 256)      v = Wq[(((size_t)h * NJ + n) * 256 + d) * FD + f];
        else if (j < 512) v = Wk[((size_t)h * 256 + d) * FD + f];
        else              v = Wv[((size_t)h * 256 + d) * FD + f];
        g_Wh[i] = __float2half_rn(v);
    }
}
__global__ void prep_b_kernel(const float* __restrict__ bq, const float* __restrict__ bk,
                              const float* __restrict__ bv) {
    int i = blockIdx.x * blockDim.x + threadIdx.x;
    if (i < NJ * OUTJ) {
        int n = i / OUTJ, j = i % OUTJ, h = (j >> 5) & 7, f = j & 31;
        float v;
        if (j < 256)      v = bq[(h * NJ + n) * FD + f];
        else if (j < 512) v = bk[h * FD + f];
        else              v = bv[h * FD + f];
        g_bias[i] = v;
    }
}

// ------------------ K1: fp16 mma QKV GEMM, 64-k chunks, 2 CTAs/SM ------------
// 288 CTAs = 24 joints x 6 col-blocks x 2 M-halves. CTA 128x128, warps 4m x 2n.
// Chunk = 128 rows x 64 k; A rows padded 144B. 2 stages, distance 1.
// Epilogue: all outputs fp16 (branch-free half2 stores).
#define OFF_B    0          // 128 x 528 = 67584
#define OFF_A    67584      // 2 x 18432 = 36864
#define OFF_BIAS 104448     // 512
#define SMEM1    104960
#define ASTG     18432

__global__ void __launch_bounds__(256, 2)
qkv_gemm11_kernel() {
    extern __shared__ char sm[];
    const uint32_t sb = smem_u32(sm);
    float* bias_s = (float*)(sm + OFF_BIAS);
    const int tid = threadIdx.x, warp = tid >> 5, lane = tid & 31;
    const int g = lane >> 2, tg = lane & 3;
    const int wm = warp >> 1, wn = warp & 1;
    const int bx = blockIdx.x;
    const int nj = bx / 12, rem = bx % 12;
    const int jb = rem >> 1, mh = rem & 1;
    const size_t mbase = (size_t)mh * 4096;

    {   // prologue: group0 = B panel + A chunk0
        const __half* W = g_Wh + (size_t)(nj * OUTJ + jb * 128) * 256;
#pragma unroll
        for (int it = 0; it < 16; ++it) {
            int i = tid + 256 * it;
            int row = i >> 5, c4 = i & 31;
            cp16(sb + OFF_B + (uint32_t)(row * 528 + c4 * 16), W + row * 256 + c4 * 8);
        }
        if (tid < 128) bias_s[tid] = g_bias[nj * OUTJ + jb * 128 + tid];
        const __half* xb = g_xh + mbase * JD + (size_t)nj * 256;
#pragma unroll
        for (int it = 0; it < 4; ++it) {
            int i = tid + 256 * it;
            int row = i >> 3, c4 = i & 7;
            cp16(sb + OFF_A + (uint32_t)(row * 144 + c4 * 16), xb + (size_t)row * JD + c4 * 8);
        }
        CPC();
    }

    float acc[2][8][4];
#pragma unroll
    for (int mt = 0; mt < 2; ++mt)
#pragma unroll
        for (int nt = 0; nt < 8; ++nt)
#pragma unroll
            for (int r = 0; r < 4; ++r) acc[mt][nt][r] = 0.f;

    uint32_t aRow[2], bRow[8];
#pragma unroll
    for (int mt = 0; mt < 2; ++mt)
        aRow[mt] = (uint32_t)((wm * 32 + mt * 16 + g) * 144 + 4 * tg);
#pragma unroll
    for (int nt = 0; nt < 8; ++nt)
        bRow[nt] = (uint32_t)((wn * 64 + nt * 8 + g) * 528 + 4 * tg);

#pragma unroll 1
    for (int c = 0; c < 128; ++c) {           // chunk = (mtile c>>2, kb c&3)
        CPW(0);
        __syncthreads();
        if (c + 1 < 128) {
            int cn = c + 1;
            const __half* xb = g_xh + (mbase + (size_t)(cn >> 2) * 128) * JD +
                               (size_t)nj * 256 + (cn & 3) * 64;
            uint32_t stb = sb + OFF_A + (uint32_t)(cn & 1) * ASTG;
#pragma unroll
            for (int it = 0; it < 4; ++it) {
                int i = tid + 256 * it;
                int row = i >> 3, c4 = i & 7;
                cp16(stb + (uint32_t)(row * 144 + c4 * 16), xb + (size_t)row * JD + c4 * 8);
            }
        }
        CPC();

        const char* A0 = sm + OFF_A + (c & 1) * ASTG;
        const char* Bc = sm + OFF_B + (c & 3) * 128;
#pragma unroll
        for (int s = 0; s < 4; ++s) {
            const uint32_t kb = (uint32_t)(s * 32);
            unsigned bfr[8][2];
#pragma unroll
            for (int nt = 0; nt < 8; ++nt) {
                bfr[nt][0] = *(const unsigned*)(Bc + bRow[nt] + kb);
                bfr[nt][1] = *(const unsigned*)(Bc + bRow[nt] + kb + 16);
            }
            unsigned a[2][4];
#pragma unroll
            for (int mt = 0; mt < 2; ++mt) {
                const char* ap = A0 + aRow[mt] + kb;
                a[mt][0] = *(const unsigned*)(ap);
                a[mt][1] = *(const unsigned*)(ap + 1152);
                a[mt][2] = *(const unsigned*)(ap + 16);
                a[mt][3] = *(const unsigned*)(ap + 1168);
            }
#pragma unroll
            for (int mt = 0; mt < 2; ++mt)
#pragma unroll
                for (int nt = 0; nt < 8; ++nt)
                    mma_f16(acc[mt][nt], a[mt], bfr[nt][0], bfr[nt][1]);
        }

        if ((c & 3) == 3) {                    // epilogue: all fp16
            const int rbase = (int)mbase + (c >> 2) * 128 + wm * 32 + g;
#pragma unroll
            for (int mt = 0; mt < 2; ++mt)
#pragma unroll
                for (int nt = 0; nt < 8; ++nt) {
                    int jl = wn * 64 + nt * 8 + tg * 2;
                    int jg = jb * 128 + jl;
                    int mat = jg >> 8, h = (jg >> 5) & 7, f = jg & 31;
                    float b0 = bias_s[jl], b1 = bias_s[jl + 1];
                    __half* dst = (mat == 0) ? g_Qh : ((mat == 1) ? g_Kh : g_Vh);
                    size_t o0 = (size_t)(rbase + mt * 16) * JD + h * OUTJ + nj * 32 + f;
                    *(__half2*)&dst[o0] =
                        __floats2half2_rn(acc[mt][nt][0] + b0, acc[mt][nt][1] + b1);
                    *(__half2*)&dst[o0 + 8 * JD] =
                        __floats2half2_rn(acc[mt][nt][2] + b0, acc[mt][nt][3] + b1);
                    acc[mt][nt][0] = acc[mt][nt][1] = acc[mt][nt][2] = acc[mt][nt][3] = 0.f;
                }
        }
    }
}

// -------- K2: 2-CTA/SM attention + residual + LN; all-fp16 QKV ---------------
#define GRID2   296
#define O2_K    0u          // 6144 f16 = 12288 B
#define O2_Q    12288u      // 192 x 80 B = 15360 B (fp16 padded)
#define O2_V    27648u      // 12288 B (fp16)
#define O2_ATT  39936u      // 18432 B
#define O2_RED  58368u
#define SMEM2   58624

__device__ __forceinline__ void h8f(float* q, uint4 u, float sc) {
    float2 f;
    f = __half22float2(*(__half2*)&u.x); q[0] = f.x * sc; q[1] = f.y * sc;
    f = __half22float2(*(__half2*)&u.y); q[2] = f.x * sc; q[3] = f.y * sc;
    f = __half22float2(*(__half2*)&u.z); q[4] = f.x * sc; q[5] = f.y * sc;
    f = __half22float2(*(__half2*)&u.w); q[6] = f.x * sc; q[7] = f.y * sc;
}

__global__ void __launch_bounds__(256, 2)
attn_ln9_kernel(const float* __restrict__ x, const float* __restrict__ gamma,
                const float* __restrict__ beta, float* __restrict__ y) {
    extern __shared__ float sm2[];
    float* att = sm2 + (O2_ATT / 4);
    float* red = sm2 + (O2_RED / 4);
    const uint32_t sb = smem_u32(sm2);
    const int tid = threadIdx.x, warp = tid >> 5, lane = tid & 31;
    const int t0 = blockIdx.x;
    const float SC = 0.17677669529663687f;   // 1/sqrt(32)

    {   // prologue: KQ(t0), then V(t0)
        const __half* Kg = g_Kh + (size_t)t0 * JD;
        const __half* Qg = g_Qh + (size_t)t0 * JD;
#pragma unroll
        for (int it = 0; it < 3; ++it) {
            int i = tid + 256 * it;            // 768 granules of 8 halves
            cp16(sb + O2_K + (uint32_t)i * 16, Kg + i * 8);
            cp16(sb + O2_Q + (uint32_t)((i >> 2) * 80 + (i & 3) * 16), Qg + i * 8);
        }
        CPC();
        const __half* Vg = g_Vh + (size_t)t0 * JD;
#pragma unroll
        for (int it = 0; it < 3; ++it) {
            int i = tid + 256 * it;
            cp16(sb + O2_V + (uint32_t)i * 16, Vg + i * 8);
        }
        CPC();
    }

#pragma unroll 1
    for (int t = t0; t < T_TOK; t += GRID2) {
        CPW(1);                  // KQ(t) ready
        __syncthreads();

        // ---- Phase C: scores + softmax (warp=head, lane=joint) ----
        if (lane < NJ) {
            const char* qb = (const char*)sm2 + O2_Q + (warp * NJ + lane) * 80;
            float q[32];
            h8f(q +  0, *(const uint4*)(qb +  0), SC);
            h8f(q +  8, *(const uint4*)(qb + 16), SC);
            h8f(q + 16, *(const uint4*)(qb + 32), SC);
            h8f(q + 24, *(const uint4*)(qb + 48), SC);
            const char* kp = (const char*)sm2 + O2_K + warp * 1536;   // h*768 halves
            float sc[NJ];
#pragma unroll
            for (int m = 0; m < NJ; ++m) {
                float kv[32];
                const char* kr = kp + m * 64;
                h8f(kv +  0, *(const uint4*)(kr +  0), 1.f);
                h8f(kv +  8, *(const uint4*)(kr + 16), 1.f);
                h8f(kv + 16, *(const uint4*)(kr + 32), 1.f);
                h8f(kv + 24, *(const uint4*)(kr + 48), 1.f);
                float sv = 0.f;
#pragma unroll
                for (int f = 0; f < 32; ++f) sv += q[f] * kv[f];
                sc[m] = sv;
            }
            float mx = sc[0];
#pragma unroll
            for (int m = 1; m < NJ; ++m) mx = fmaxf(mx, sc[m]);
            float sum = 0.f;
#pragma unroll
            for (int m = 0; m < NJ; ++m) { sc[m] = __expf(sc[m] - mx); sum += sc[m]; }
            const float inv = 1.f / sum;
            float* ap = att + warp * 576 + lane * 24;
#pragma unroll
            for (int mq = 0; mq < 6; ++mq)
                *(float4*)&ap[mq * 4] = make_float4(sc[4*mq]*inv, sc[4*mq+1]*inv,
                                                   sc[4*mq+2]*inv, sc[4*mq+3]*inv);
        }
        __syncthreads();         // att visible; K/Q free

        const int tn = t + GRID2;
        if (tn < T_TOK) {        // prefetch KQ(t+1) — overlaps phase E
            const __half* Kg = g_Kh + (size_t)tn * JD;
            const __half* Qg = g_Qh + (size_t)tn * JD;
#pragma unroll
            for (int it = 0; it < 3; ++it) {
                int i = tid + 256 * it;
                cp16(sb + O2_K + (uint32_t)i * 16, Kg + i * 8);
                cp16(sb + O2_Q + (uint32_t)((i >> 2) * 80 + (i & 3) * 16), Qg + i * 8);
            }
        }
        CPC();
        CPW(1);                  // V(t) ready
        __syncthreads();

        // ---- Phase E: AV + residual (thread = channel (h,f)) ----
        float out[NJ];
        {
            const float* xg = x + (size_t)t * JD + tid;
#pragma unroll
            for (int n = 0; n < NJ; ++n) out[n] = xg[n * 256];
        }
        {
            const __half* vp = (const __half*)((const char*)sm2 + O2_V) + warp * OUTJ + lane;
            const float* ap = att + warp * 576;
#pragma unroll
            for (int mq = 0; mq < 6; ++mq) {
                float v0 = __half2float(vp[(4*mq+0) * 32]);
                float v1 = __half2float(vp[(4*mq+1) * 32]);
                float v2 = __half2float(vp[(4*mq+2) * 32]);
                float v3 = __half2float(vp[(4*mq+3) * 32]);
#pragma unroll
                for (int n = 0; n < NJ; ++n) {
                    float4 a = *(const float4*)&ap[n * 24 + mq * 4];
                    out[n] += a.x*v0 + a.y*v1 + a.z*v2 + a.w*v3;
                }
            }
        }
        // ---- LN over 6144 ----
        float s1 = 0.f, s2 = 0.f;
#pragma unroll
        for (int n = 0; n < NJ; ++n) { s1 += out[n]; s2 += out[n] * out[n]; }
#pragma unroll
        for (int o = 16; o; o >>= 1) {
            s1 += __shfl_xor_sync(0xffffffffu, s1, o);
            s2 += __shfl_xor_sync(0xffffffffu, s2, o);
        }
        if (lane == 0) { red[warp] = s1; red[8 + warp] = s2; }
        __syncthreads();

        if (tn < T_TOK) {        // prefetch V(t+1) — overlaps epilogue
            const __half* Vg = g_Vh + (size_t)tn * JD;
#pragma unroll
            for (int it = 0; it < 3; ++it) {
                int i = tid + 256 * it;
                cp16(sb + O2_V + (uint32_t)i * 16, Vg + i * 8);
            }
        }
        CPC();

        float S1 = 0.f, S2 = 0.f;
#pragma unroll
        for (int w = 0; w < 8; ++w) { S1 += red[w]; S2 += red[8 + w]; }
        const float mu = S1 * (1.0f / JD);
        const float var = S2 * (1.0f / JD) - mu * mu;
        const float rstd = rsqrtf(var + 1e-5f);
        {
            float* yt = y + (size_t)t * JD + tid;
            const float* gp = gamma + tid;
            const float* bp = beta + tid;
#pragma unroll
            for (int n = 0; n < NJ; ++n)
                yt[n * 256] = (out[n] - mu) * rstd * gp[n * 256] + bp[n * 256];
        }
    }
}

// ---------------------------------------------------------------------------
extern "C" void kernel_launch(void* const* d_in, const int* in_sizes, int n_in,
                              void* d_out, int out_size) {
    const float* x     = (const float*)d_in[0];
    const float* Wq    = (const float*)d_in[1];
    const float* bq    = (const float*)d_in[2];
    const float* Wk    = (const float*)d_in[3];
    const float* bk    = (const float*)d_in[4];
    const float* Wv    = (const float*)d_in[5];
    const float* bv    = (const float*)d_in[6];
    const float* gamma = (const float*)d_in[7];
    const float* beta  = (const float*)d_in[8];
    float* y = (float*)d_out;

    cudaFuncSetAttribute(qkv_gemm11_kernel, cudaFuncAttributeMaxDynamicSharedMemorySize, SMEM1);
    cudaFuncSetAttribute(attn_ln9_kernel,   cudaFuncAttributeMaxDynamicSharedMemorySize, SMEM2);

    prep_x_kernel<<<24576, 256>>>(x);
    prep_w_kernel<<<4608, 256>>>(Wq, Wk, Wv);
    prep_b_kernel<<<72, 256>>>(bq, bk, bv);
    qkv_gemm11_kernel<<<288, 256, SMEM1>>>();
    attn_ln9_kernel<<<GRID2, 256, SMEM2>>>(x, gamma, beta, y);
}

// round 16
// speedup vs baseline: 1.0207x; 1.0207x over previous
#include <cuda_runtime.h>
#include <cuda_fp16.h>
#include <cstdint>
#include <cstddef>

#define T_TOK 8192
#define NJ    24
#define NH    8
#define FD    32
#define JD    6144
#define OUTJ  768

__device__ __half g_Qh[(size_t)T_TOK * JD];        // q fp16 [t][h][n][f]
__device__ float  g_K [(size_t)T_TOK * JD];        // k fp32
__device__ __half g_Vh[(size_t)T_TOK * JD];        // v fp16
__device__ __half g_xh[(size_t)T_TOK * JD];        // x fp16
__device__ __half g_Wh[(size_t)NJ * OUTJ * 256];   // [n][j][d] fp16
__device__ float  g_bias[NJ * OUTJ];

__device__ __forceinline__ uint32_t smem_u32(const void* p) {
    uint32_t a;
    asm("{ .reg .u64 t; cvta.to.shared.u64 t, %1; cvt.u32.u64 %0, t; }" : "=r"(a) : "l"(p));
    return a;
}
__device__ __forceinline__ void mma_f16(float* d, const unsigned* a, unsigned b0, unsigned b1) {
    asm volatile(
        "mma.sync.aligned.m16n8k16.row.col.f32.f16.f16.f32 "
        "{%0,%1,%2,%3}, {%4,%5,%6,%7}, {%8,%9}, {%0,%1,%2,%3};\n"
        : "+f"(d[0]), "+f"(d[1]), "+f"(d[2]), "+f"(d[3])
        : "r"(a[0]), "r"(a[1]), "r"(a[2]), "r"(a[3]), "r"(b0), "r"(b1));
}
__device__ __forceinline__ void cp16(uint32_t d, const void* s) {
    asm volatile("cp.async.cg.shared.global [%0], [%1], 16;" :: "r"(d), "l"(s));
}
#define CPC()  asm volatile("cp.async.commit_group;" ::: "memory")
#define CPW(n) asm volatile("cp.async.wait_group %0;" :: "n"(n) : "memory")

// ------------------------------- prep ---------------------------------------
__global__ void prep_x_kernel(const float* __restrict__ x) {
    size_t i = (size_t)blockIdx.x * blockDim.x + threadIdx.x;
    const size_t total8 = (size_t)T_TOK * JD / 8;
    if (i < total8) {
        float4 v0 = ((const float4*)x)[2 * i];
        float4 v1 = ((const float4*)x)[2 * i + 1];
        __half2 h0 = __floats2half2_rn(v0.x, v0.y);
        __half2 h1 = __floats2half2_rn(v0.z, v0.w);
        __half2 h2 = __floats2half2_rn(v1.x, v1.y);
        __half2 h3 = __floats2half2_rn(v1.z, v1.w);
        uint4 o;
        o.x = *(uint32_t*)&h0; o.y = *(uint32_t*)&h1;
        o.z = *(uint32_t*)&h2; o.w = *(uint32_t*)&h3;
        ((uint4*)g_xh)[i] = o;
    }
}
__global__ void prep_w_kernel(const float* __restrict__ Wq, const float* __restrict__ Wk,
                              const float* __restrict__ Wv) {
    const size_t total = (size_t)NJ * OUTJ * 256;
    for (size_t i = (size_t)blockIdx.x * blockDim.x + threadIdx.x; i < total;
         i += (size_t)gridDim.x * blockDim.x) {
        int d = (int)(i & 255);
        size_t nj = i >> 8;
        int j = (int)(nj % OUTJ), n = (int)(nj / OUTJ);
        int h = (j >> 5) & 7, f = j & 31;
        float v;
        if (j < 256)      v = Wq[(((size_t)h * NJ + n) * 256 + d) * FD + f];
        else if (j < 512) v = Wk[((size_t)h * 256 + d) * FD + f];
        else              v = Wv[((size_t)h * 256 + d) * FD + f];
        g_Wh[i] = __float2half_rn(v);
    }
}
__global__ void prep_b_kernel(const float* __restrict__ bq, const float* __restrict__ bk,
                              const float* __restrict__ bv) {
    int i = blockIdx.x * blockDim.x + threadIdx.x;
    if (i < NJ * OUTJ) {
        int n = i / OUTJ, j = i % OUTJ, h = (j >> 5) & 7, f = j & 31;
        float v;
        if (j < 256)      v = bq[(h * NJ + n) * FD + f];
        else if (j < 512) v = bk[h * FD + f];
        else              v = bv[h * FD + f];
        g_bias[i] = v;
    }
}

// ------------------ K1: fp16 mma QKV GEMM, 64-k chunks, 2 CTAs/SM ------------
// (R14 proven config) 288 CTAs; CTA 128x128; chunk 128x64; 2 stages, dist 1.
#define OFF_B    0          // 128 x 528 = 67584
#define OFF_A    67584      // 2 x 18432 = 36864
#define OFF_BIAS 104448     // 512
#define SMEM1    104960
#define ASTG     18432

__global__ void __launch_bounds__(256, 2)
qkv_gemm10_kernel() {
    extern __shared__ char sm[];
    const uint32_t sb = smem_u32(sm);
    float* bias_s = (float*)(sm + OFF_BIAS);
    const int tid = threadIdx.x, warp = tid >> 5, lane = tid & 31;
    const int g = lane >> 2, tg = lane & 3;
    const int wm = warp >> 1, wn = warp & 1;
    const int bx = blockIdx.x;
    const int nj = bx / 12, rem = bx % 12;
    const int jb = rem >> 1, mh = rem & 1;
    const size_t mbase = (size_t)mh * 4096;

    {   // prologue: group0 = B panel + A chunk0
        const __half* W = g_Wh + (size_t)(nj * OUTJ + jb * 128) * 256;
#pragma unroll
        for (int it = 0; it < 16; ++it) {
            int i = tid + 256 * it;
            int row = i >> 5, c4 = i & 31;
            cp16(sb + OFF_B + (uint32_t)(row * 528 + c4 * 16), W + row * 256 + c4 * 8);
        }
        if (tid < 128) bias_s[tid] = g_bias[nj * OUTJ + jb * 128 + tid];
        const __half* xb = g_xh + mbase * JD + (size_t)nj * 256;
#pragma unroll
        for (int it = 0; it < 4; ++it) {
            int i = tid + 256 * it;
            int row = i >> 3, c4 = i & 7;
            cp16(sb + OFF_A + (uint32_t)(row * 144 + c4 * 16), xb + (size_t)row * JD + c4 * 8);
        }
        CPC();
    }

    float acc[2][8][4];
#pragma unroll
    for (int mt = 0; mt < 2; ++mt)
#pragma unroll
        for (int nt = 0; nt < 8; ++nt)
#pragma unroll
            for (int r = 0; r < 4; ++r) acc[mt][nt][r] = 0.f;

    uint32_t aRow[2], bRow[8];
#pragma unroll
    for (int mt = 0; mt < 2; ++mt)
        aRow[mt] = (uint32_t)((wm * 32 + mt * 16 + g) * 144 + 4 * tg);
#pragma unroll
    for (int nt = 0; nt < 8; ++nt)
        bRow[nt] = (uint32_t)((wn * 64 + nt * 8 + g) * 528 + 4 * tg);

#pragma unroll 1
    for (int c = 0; c < 128; ++c) {           // chunk = (mtile c>>2, kb c&3)
        CPW(0);
        __syncthreads();
        if (c + 1 < 128) {
            int cn = c + 1;
            const __half* xb = g_xh + (mbase + (size_t)(cn >> 2) * 128) * JD +
                               (size_t)nj * 256 + (cn & 3) * 64;
            uint32_t stb = sb + OFF_A + (uint32_t)(cn & 1) * ASTG;
#pragma unroll
            for (int it = 0; it < 4; ++it) {
                int i = tid + 256 * it;
                int row = i >> 3, c4 = i & 7;
                cp16(stb + (uint32_t)(row * 144 + c4 * 16), xb + (size_t)row * JD + c4 * 8);
            }
        }
        CPC();

        const char* A0 = sm + OFF_A + (c & 1) * ASTG;
        const char* Bc = sm + OFF_B + (c & 3) * 128;
#pragma unroll
        for (int s = 0; s < 4; ++s) {
            const uint32_t kb = (uint32_t)(s * 32);
            unsigned bfr[8][2];
#pragma unroll
            for (int nt = 0; nt < 8; ++nt) {
                bfr[nt][0] = *(const unsigned*)(Bc + bRow[nt] + kb);
                bfr[nt][1] = *(const unsigned*)(Bc + bRow[nt] + kb + 16);
            }
            unsigned a[2][4];
#pragma unroll
            for (int mt = 0; mt < 2; ++mt) {
                const char* ap = A0 + aRow[mt] + kb;
                a[mt][0] = *(const unsigned*)(ap);
                a[mt][1] = *(const unsigned*)(ap + 1152);
                a[mt][2] = *(const unsigned*)(ap + 16);
                a[mt][3] = *(const unsigned*)(ap + 1168);
            }
#pragma unroll
            for (int mt = 0; mt < 2; ++mt)
#pragma unroll
                for (int nt = 0; nt < 8; ++nt)
                    mma_f16(acc[mt][nt], a[mt], bfr[nt][0], bfr[nt][1]);
        }

        if ((c & 3) == 3) {                    // epilogue: Q/V fp16, K fp32
            const int rbase = (int)mbase + (c >> 2) * 128 + wm * 32 + g;
#pragma unroll
            for (int mt = 0; mt < 2; ++mt)
#pragma unroll
                for (int nt = 0; nt < 8; ++nt) {
                    int jl = wn * 64 + nt * 8 + tg * 2;
                    int jg = jb * 128 + jl;
                    int mat = jg >> 8, h = (jg >> 5) & 7, f = jg & 31;
                    float b0 = bias_s[jl], b1 = bias_s[jl + 1];
                    size_t o0 = (size_t)(rbase + mt * 16) * JD + h * OUTJ + nj * 32 + f;
                    if (mat == 1) {
                        *(float2*)&g_K[o0] =
                            make_float2(acc[mt][nt][0] + b0, acc[mt][nt][1] + b1);
                        *(float2*)&g_K[o0 + 8 * JD] =
                            make_float2(acc[mt][nt][2] + b0, acc[mt][nt][3] + b1);
                    } else {
                        __half* dst = (mat == 0) ? g_Qh : g_Vh;
                        *(__half2*)&dst[o0] =
                            __floats2half2_rn(acc[mt][nt][0] + b0, acc[mt][nt][1] + b1);
                        *(__half2*)&dst[o0 + 8 * JD] =
                            __floats2half2_rn(acc[mt][nt][2] + b0, acc[mt][nt][3] + b1);
                    }
                    acc[mt][nt][0] = acc[mt][nt][1] = acc[mt][nt][2] = acc[mt][nt][3] = 0.f;
                }
        }
    }
}

// -------- K2: 2-CTA/SM attention + residual + LN; fp16 x residual ------------
// (R14 structure; only change: residual reads g_xh instead of fp32 x)
#define GRID2   296
#define O2_K    0u          // 24576 B (fp32)
#define O2_Q    24576u      // 192 x 80 B (fp16 padded)
#define O2_V    39936u      // 12288 B (fp16)
#define O2_ATT  52224u      // 18432 B
#define O2_RED  70656u
#define SMEM2   70912

__device__ __forceinline__ void h8f(float* q, uint4 u, float sc) {
    float2 f;
    f = __half22float2(*(__half2*)&u.x); q[0] = f.x * sc; q[1] = f.y * sc;
    f = __half22float2(*(__half2*)&u.y); q[2] = f.x * sc; q[3] = f.y * sc;
    f = __half22float2(*(__half2*)&u.z); q[4] = f.x * sc; q[5] = f.y * sc;
    f = __half22float2(*(__half2*)&u.w); q[6] = f.x * sc; q[7] = f.y * sc;
}

__global__ void __launch_bounds__(256, 2)
attn_ln10_kernel(const float* __restrict__ gamma,
                 const float* __restrict__ beta, float* __restrict__ y) {
    extern __shared__ float sm2[];
    float* att = sm2 + (O2_ATT / 4);
    float* red = sm2 + (O2_RED / 4);
    const uint32_t sb = smem_u32(sm2);
    const int tid = threadIdx.x, warp = tid >> 5, lane = tid & 31;
    const int t0 = blockIdx.x;
    const float SC = 0.17677669529663687f;   // 1/sqrt(32)

    {   // prologue: KQ(t0), then V(t0)
        const float*  Kg = g_K  + (size_t)t0 * JD;
        const __half* Qg = g_Qh + (size_t)t0 * JD;
#pragma unroll
        for (int it = 0; it < 6; ++it) {
            int i = tid + 256 * it;
            cp16(sb + O2_K + (uint32_t)i * 16, Kg + i * 4);
        }
#pragma unroll
        for (int it = 0; it < 3; ++it) {
            int i = tid + 256 * it;
            cp16(sb + O2_Q + (uint32_t)((i >> 2) * 80 + (i & 3) * 16), Qg + i * 8);
        }
        CPC();
        const __half* Vg = g_Vh + (size_t)t0 * JD;
#pragma unroll
        for (int it = 0; it < 3; ++it) {
            int i = tid + 256 * it;
            cp16(sb + O2_V + (uint32_t)i * 16, Vg + i * 8);
        }
        CPC();
    }

#pragma unroll 1
    for (int t = t0; t < T_TOK; t += GRID2) {
        CPW(1);                  // KQ(t) ready
        __syncthreads();

        // ---- Phase C: scores + softmax (warp=head, lane=joint) ----
        if (lane < NJ) {
            const char* qb = (const char*)sm2 + O2_Q + (warp * NJ + lane) * 80;
            float q[32];
            h8f(q +  0, *(const uint4*)(qb +  0), SC);
            h8f(q +  8, *(const uint4*)(qb + 16), SC);
            h8f(q + 16, *(const uint4*)(qb + 32), SC);
            h8f(q + 24, *(const uint4*)(qb + 48), SC);
            const float* kp = sm2 + warp * OUTJ;
            float sc[NJ];
#pragma unroll
            for (int m = 0; m < NJ; ++m) {
                const float4* kr = (const float4*)(kp + m * 32);
                float sv = 0.f;
#pragma unroll
                for (int f4 = 0; f4 < 8; ++f4) {
                    float4 kv = kr[f4];
                    sv += q[4*f4+0]*kv.x + q[4*f4+1]*kv.y + q[4*f4+2]*kv.z + q[4*f4+3]*kv.w;
                }
                sc[m] = sv;
            }
            float mx = sc[0];
#pragma unroll
            for (int m = 1; m < NJ; ++m) mx = fmaxf(mx, sc[m]);
            float sum = 0.f;
#pragma unroll
            for (int m = 0; m < NJ; ++m) { sc[m] = __expf(sc[m] - mx); sum += sc[m]; }
            const float inv = 1.f / sum;
            float* ap = att + warp * 576 + lane * 24;
#pragma unroll
            for (int mq = 0; mq < 6; ++mq)
                *(float4*)&ap[mq * 4] = make_float4(sc[4*mq]*inv, sc[4*mq+1]*inv,
                                                   sc[4*mq+2]*inv, sc[4*mq+3]*inv);
        }
        __syncthreads();         // att visible; K/Q free

        const int tn = t + GRID2;
        if (tn < T_TOK) {        // prefetch KQ(t+1) — overlaps phase E
            const float*  Kg = g_K  + (size_t)tn * JD;
            const __half* Qg = g_Qh + (size_t)tn * JD;
#pragma unroll
            for (int it = 0; it < 6; ++it) {
                int i = tid + 256 * it;
                cp16(sb + O2_K + (uint32_t)i * 16, Kg + i * 4);
            }
#pragma unroll
            for (int it = 0; it < 3; ++it) {
                int i = tid + 256 * it;
                cp16(sb + O2_Q + (uint32_t)((i >> 2) * 80 + (i & 3) * 16), Qg + i * 8);
            }
        }
        CPC();
        CPW(1);                  // V(t) ready
        __syncthreads();

        // ---- Phase E: AV + residual (thread = channel (h,f)) ----
        float out[NJ];
        {
            const __half* xg = g_xh + (size_t)t * JD + tid;   // fp16 residual
#pragma unroll
            for (int n = 0; n < NJ; ++n) out[n] = __half2float(xg[n * 256]);
        }
        {
            const __half* vp = (const __half*)((const char*)sm2 + O2_V) + warp * OUTJ + lane;
            const float* ap = att + warp * 576;
#pragma unroll
            for (int mq = 0; mq < 6; ++mq) {
                float v0 = __half2float(vp[(4*mq+0) * 32]);
                float v1 = __half2float(vp[(4*mq+1) * 32]);
                float v2 = __half2float(vp[(4*mq+2) * 32]);
                float v3 = __half2float(vp[(4*mq+3) * 32]);
#pragma unroll
                for (int n = 0; n < NJ; ++n) {
                    float4 a = *(const float4*)&ap[n * 24 + mq * 4];
                    out[n] += a.x*v0 + a.y*v1 + a.z*v2 + a.w*v3;
                }
            }
        }
        // ---- LN over 6144 ----
        float s1 = 0.f, s2 = 0.f;
#pragma unroll
        for (int n = 0; n < NJ; ++n) { s1 += out[n]; s2 += out[n] * out[n]; }
#pragma unroll
        for (int o = 16; o; o >>= 1) {
            s1 += __shfl_xor_sync(0xffffffffu, s1, o);
            s2 += __shfl_xor_sync(0xffffffffu, s2, o);
        }
        if (lane == 0) { red[warp] = s1; red[8 + warp] = s2; }
        __syncthreads();

        if (tn < T_TOK) {        // prefetch V(t+1) — overlaps epilogue
            const __half* Vg = g_Vh + (size_t)tn * JD;
#pragma unroll
            for (int it = 0; it < 3; ++it) {
                int i = tid + 256 * it;
                cp16(sb + O2_V + (uint32_t)i * 16, Vg + i * 8);
            }
        }
        CPC();

        float S1 = 0.f, S2 = 0.f;
#pragma unroll
        for (int w = 0; w < 8; ++w) { S1 += red[w]; S2 += red[8 + w]; }
        const float mu = S1 * (1.0f / JD);
        const float var = S2 * (1.0f / JD) - mu * mu;
        const float rstd = rsqrtf(var + 1e-5f);
        {
            float* yt = y + (size_t)t * JD + tid;
            const float* gp = gamma + tid;
            const float* bp = beta + tid;
#pragma unroll
            for (int n = 0; n < NJ; ++n)
                yt[n * 256] = (out[n] - mu) * rstd * gp[n * 256] + bp[n * 256];
        }
    }
}

// ---------------------------------------------------------------------------
extern "C" void kernel_launch(void* const* d_in, const int* in_sizes, int n_in,
                              void* d_out, int out_size) {
    const float* x     = (const float*)d_in[0];
    const float* Wq    = (const float*)d_in[1];
    const float* bq    = (const float*)d_in[2];
    const float* Wk    = (const float*)d_in[3];
    const float* bk    = (const float*)d_in[4];
    const float* Wv    = (const float*)d_in[5];
    const float* bv    = (const float*)d_in[6];
    const float* gamma = (const float*)d_in[7];
    const float* beta  = (const float*)d_in[8];
    float* y = (float*)d_out;

    cudaFuncSetAttribute(qkv_gemm10_kernel, cudaFuncAttributeMaxDynamicSharedMemorySize, SMEM1);
    cudaFuncSetAttribute(attn_ln10_kernel,  cudaFuncAttributeMaxDynamicSharedMemorySize, SMEM2);

    prep_x_kernel<<<24576, 256>>>(x);
    prep_w_kernel<<<4608, 256>>>(Wq, Wk, Wv);
    prep_b_kernel<<<72, 256>>>(bq, bk, bv);
    qkv_gemm10_kernel<<<288, 256, SMEM1>>>();
    attn_ln10_kernel<<<GRID2, 256, SMEM2>>>(gamma, beta, y);
}

// round 17
// speedup vs baseline: 1.0259x; 1.0050x over previous
#include <cuda_runtime.h>
#include <cuda_fp16.h>
#include <cstdint>
#include <cstddef>

#define T_TOK 8192
#define NJ    24
#define NH    8
#define FD    32
#define JD    6144
#define OUTJ  768

__device__ __half g_Qh[(size_t)T_TOK * JD];        // q fp16 [t][h][n][f]
__device__ float  g_K [(size_t)T_TOK * JD];        // k fp32
__device__ __half g_Vh[(size_t)T_TOK * JD];        // v fp16
__device__ __half g_xh[(size_t)T_TOK * JD];        // x fp16
__device__ __half g_Wh[(size_t)NJ * OUTJ * 256];   // [n][j][d] fp16
__device__ float  g_bias[NJ * OUTJ];

__device__ __forceinline__ uint32_t smem_u32(const void* p) {
    uint32_t a;
    asm("{ .reg .u64 t; cvta.to.shared.u64 t, %1; cvt.u32.u64 %0, t; }" : "=r"(a) : "l"(p));
    return a;
}
__device__ __forceinline__ void mma_f16(float* d, const unsigned* a, unsigned b0, unsigned b1) {
    asm volatile(
        "mma.sync.aligned.m16n8k16.row.col.f32.f16.f16.f32 "
        "{%0,%1,%2,%3}, {%4,%5,%6,%7}, {%8,%9}, {%0,%1,%2,%3};\n"
        : "+f"(d[0]), "+f"(d[1]), "+f"(d[2]), "+f"(d[3])
        : "r"(a[0]), "r"(a[1]), "r"(a[2]), "r"(a[3]), "r"(b0), "r"(b1));
}
__device__ __forceinline__ void cp16(uint32_t d, const void* s) {
    asm volatile("cp.async.cg.shared.global [%0], [%1], 16;" :: "r"(d), "l"(s));
}
#define CPC()  asm volatile("cp.async.commit_group;" ::: "memory")
#define CPW(n) asm volatile("cp.async.wait_group %0;" :: "n"(n) : "memory")

// ------------------------------- prep ---------------------------------------
__global__ void prep_x_kernel(const float* __restrict__ x) {
    size_t i = (size_t)blockIdx.x * blockDim.x + threadIdx.x;
    const size_t total8 = (size_t)T_TOK * JD / 8;
    if (i < total8) {
        float4 v0 = ((const float4*)x)[2 * i];
        float4 v1 = ((const float4*)x)[2 * i + 1];
        __half2 h0 = __floats2half2_rn(v0.x, v0.y);
        __half2 h1 = __floats2half2_rn(v0.z, v0.w);
        __half2 h2 = __floats2half2_rn(v1.x, v1.y);
        __half2 h3 = __floats2half2_rn(v1.z, v1.w);
        uint4 o;
        o.x = *(uint32_t*)&h0; o.y = *(uint32_t*)&h1;
        o.z = *(uint32_t*)&h2; o.w = *(uint32_t*)&h3;
        ((uint4*)g_xh)[i] = o;
    }
}
__global__ void prep_w_kernel(const float* __restrict__ Wq, const float* __restrict__ Wk,
                              const float* __restrict__ Wv) {
    const size_t total = (size_t)NJ * OUTJ * 256;
    for (size_t i = (size_t)blockIdx.x * blockDim.x + threadIdx.x; i < total;
         i += (size_t)gridDim.x * blockDim.x) {
        int d = (int)(i & 255);
        size_t nj = i >> 8;
        int j = (int)(nj % OUTJ), n = (int)(nj / OUTJ);
        int h = (j >> 5) & 7, f = j & 31;
        float v;
        if (j < 256)      v = Wq[(((size_t)h * NJ + n) * 256 + d) * FD + f];
        else if (j < 512) v = Wk[((size_t)h * 256 + d) * FD + f];
        else              v = Wv[((size_t)h * 256 + d) * FD + f];
        g_Wh[i] = __float2half_rn(v);
    }
}
__global__ void prep_b_kernel(const float* __restrict__ bq, const float* __restrict__ bk,
                              const float* __restrict__ bv) {
    int i = blockIdx.x * blockDim.x + threadIdx.x;
    if (i < NJ * OUTJ) {
        int n = i / OUTJ, j = i % OUTJ, h = (j >> 5) & 7, f = j & 31;
        float v;
        if (j < 256)      v = bq[(h * NJ + n) * FD + f];
        else if (j < 512) v = bk[h * FD + f];
        else              v = bv[h * FD + f];
        g_bias[i] = v;
    }
}

// ------------------ K1: fp16 mma QKV GEMM, 64-k chunks, 2 CTAs/SM ------------
// (R14 proven config) 288 CTAs; CTA 128x128; chunk 128x64; 2 stages, dist 1.
#define OFF_B    0          // 128 x 528 = 67584
#define OFF_A    67584      // 2 x 18432 = 36864
#define OFF_BIAS 104448     // 512
#define SMEM1    104960
#define ASTG     18432

__global__ void __launch_bounds__(256, 2)
qkv_gemm10_kernel() {
    extern __shared__ char sm[];
    const uint32_t sb = smem_u32(sm);
    float* bias_s = (float*)(sm + OFF_BIAS);
    const int tid = threadIdx.x, warp = tid >> 5, lane = tid & 31;
    const int g = lane >> 2, tg = lane & 3;
    const int wm = warp >> 1, wn = warp & 1;
    const int bx = blockIdx.x;
    const int nj = bx / 12, rem = bx % 12;
    const int jb = rem >> 1, mh = rem & 1;
    const size_t mbase = (size_t)mh * 4096;

    {   // prologue: group0 = B panel + A chunk0
        const __half* W = g_Wh + (size_t)(nj * OUTJ + jb * 128) * 256;
#pragma unroll
        for (int it = 0; it < 16; ++it) {
            int i = tid + 256 * it;
            int row = i >> 5, c4 = i & 31;
            cp16(sb + OFF_B + (uint32_t)(row * 528 + c4 * 16), W + row * 256 + c4 * 8);
        }
        if (tid < 128) bias_s[tid] = g_bias[nj * OUTJ + jb * 128 + tid];
        const __half* xb = g_xh + mbase * JD + (size_t)nj * 256;
#pragma unroll
        for (int it = 0; it < 4; ++it) {
            int i = tid + 256 * it;
            int row = i >> 3, c4 = i & 7;
            cp16(sb + OFF_A + (uint32_t)(row * 144 + c4 * 16), xb + (size_t)row * JD + c4 * 8);
        }
        CPC();
    }

    float acc[2][8][4];
#pragma unroll
    for (int mt = 0; mt < 2; ++mt)
#pragma unroll
        for (int nt = 0; nt < 8; ++nt)
#pragma unroll
            for (int r = 0; r < 4; ++r) acc[mt][nt][r] = 0.f;

    uint32_t aRow[2], bRow[8];
#pragma unroll
    for (int mt = 0; mt < 2; ++mt)
        aRow[mt] = (uint32_t)((wm * 32 + mt * 16 + g) * 144 + 4 * tg);
#pragma unroll
    for (int nt = 0; nt < 8; ++nt)
        bRow[nt] = (uint32_t)((wn * 64 + nt * 8 + g) * 528 + 4 * tg);

#pragma unroll 1
    for (int c = 0; c < 128; ++c) {           // chunk = (mtile c>>2, kb c&3)
        CPW(0);
        __syncthreads();
        if (c + 1 < 128) {
            int cn = c + 1;
            const __half* xb = g_xh + (mbase + (size_t)(cn >> 2) * 128) * JD +
                               (size_t)nj * 256 + (cn & 3) * 64;
            uint32_t stb = sb + OFF_A + (uint32_t)(cn & 1) * ASTG;
#pragma unroll
            for (int it = 0; it < 4; ++it) {
                int i = tid + 256 * it;
                int row = i >> 3, c4 = i & 7;
                cp16(stb + (uint32_t)(row * 144 + c4 * 16), xb + (size_t)row * JD + c4 * 8);
            }
        }
        CPC();

        const char* A0 = sm + OFF_A + (c & 1) * ASTG;
        const char* Bc = sm + OFF_B + (c & 3) * 128;
#pragma unroll
        for (int s = 0; s < 4; ++s) {
            const uint32_t kb = (uint32_t)(s * 32);
            unsigned bfr[8][2];
#pragma unroll
            for (int nt = 0; nt < 8; ++nt) {
                bfr[nt][0] = *(const unsigned*)(Bc + bRow[nt] + kb);
                bfr[nt][1] = *(const unsigned*)(Bc + bRow[nt] + kb + 16);
            }
            unsigned a[2][4];
#pragma unroll
            for (int mt = 0; mt < 2; ++mt) {
                const char* ap = A0 + aRow[mt] + kb;
                a[mt][0] = *(const unsigned*)(ap);
                a[mt][1] = *(const unsigned*)(ap + 1152);
                a[mt][2] = *(const unsigned*)(ap + 16);
                a[mt][3] = *(const unsigned*)(ap + 1168);
            }
#pragma unroll
            for (int mt = 0; mt < 2; ++mt)
#pragma unroll
                for (int nt = 0; nt < 8; ++nt)
                    mma_f16(acc[mt][nt], a[mt], bfr[nt][0], bfr[nt][1]);
        }

        if ((c & 3) == 3) {                    // epilogue: Q/V fp16, K fp32
            const int rbase = (int)mbase + (c >> 2) * 128 + wm * 32 + g;
#pragma unroll
            for (int mt = 0; mt < 2; ++mt)
#pragma unroll
                for (int nt = 0; nt < 8; ++nt) {
                    int jl = wn * 64 + nt * 8 + tg * 2;
                    int jg = jb * 128 + jl;
                    int mat = jg >> 8, h = (jg >> 5) & 7, f = jg & 31;
                    float b0 = bias_s[jl], b1 = bias_s[jl + 1];
                    size_t o0 = (size_t)(rbase + mt * 16) * JD + h * OUTJ + nj * 32 + f;
                    if (mat == 1) {
                        *(float2*)&g_K[o0] =
                            make_float2(acc[mt][nt][0] + b0, acc[mt][nt][1] + b1);
                        *(float2*)&g_K[o0 + 8 * JD] =
                            make_float2(acc[mt][nt][2] + b0, acc[mt][nt][3] + b1);
                    } else {
                        __half* dst = (mat == 0) ? g_Qh : g_Vh;
                        *(__half2*)&dst[o0] =
                            __floats2half2_rn(acc[mt][nt][0] + b0, acc[mt][nt][1] + b1);
                        *(__half2*)&dst[o0 + 8 * JD] =
                            __floats2half2_rn(acc[mt][nt][2] + b0, acc[mt][nt][3] + b1);
                    }
                    acc[mt][nt][0] = acc[mt][nt][1] = acc[mt][nt][2] = acc[mt][nt][3] = 0.f;
                }
        }
    }
}

// -------- K2: 2-CTA/SM attention + residual + LN; fp16 x residual ------------
// (R14 structure; only change: residual reads g_xh instead of fp32 x)
#define GRID2   296
#define O2_K    0u          // 24576 B (fp32)
#define O2_Q    24576u      // 192 x 80 B (fp16 padded)
#define O2_V    39936u      // 12288 B (fp16)
#define O2_ATT  52224u      // 18432 B
#define O2_RED  70656u
#define SMEM2   70912

__device__ __forceinline__ void h8f(float* q, uint4 u, float sc) {
    float2 f;
    f = __half22float2(*(__half2*)&u.x); q[0] = f.x * sc; q[1] = f.y * sc;
    f = __half22float2(*(__half2*)&u.y); q[2] = f.x * sc; q[3] = f.y * sc;
    f = __half22float2(*(__half2*)&u.z); q[4] = f.x * sc; q[5] = f.y * sc;
    f = __half22float2(*(__half2*)&u.w); q[6] = f.x * sc; q[7] = f.y * sc;
}

__global__ void __launch_bounds__(256, 2)
attn_ln10_kernel(const float* __restrict__ gamma,
                 const float* __restrict__ beta, float* __restrict__ y) {
    extern __shared__ float sm2[];
    float* att = sm2 + (O2_ATT / 4);
    float* red = sm2 + (O2_RED / 4);
    const uint32_t sb = smem_u32(sm2);
    const int tid = threadIdx.x, warp = tid >> 5, lane = tid & 31;
    const int t0 = blockIdx.x;
    const float SC = 0.17677669529663687f;   // 1/sqrt(32)

    {   // prologue: KQ(t0), then V(t0)
        const float*  Kg = g_K  + (size_t)t0 * JD;
        const __half* Qg = g_Qh + (size_t)t0 * JD;
#pragma unroll
        for (int it = 0; it < 6; ++it) {
            int i = tid + 256 * it;
            cp16(sb + O2_K + (uint32_t)i * 16, Kg + i * 4);
        }
#pragma unroll
        for (int it = 0; it < 3; ++it) {
            int i = tid + 256 * it;
            cp16(sb + O2_Q + (uint32_t)((i >> 2) * 80 + (i & 3) * 16), Qg + i * 8);
        }
        CPC();
        const __half* Vg = g_Vh + (size_t)t0 * JD;
#pragma unroll
        for (int it = 0; it < 3; ++it) {
            int i = tid + 256 * it;
            cp16(sb + O2_V + (uint32_t)i * 16, Vg + i * 8);
        }
        CPC();
    }

#pragma unroll 1
    for (int t = t0; t < T_TOK; t += GRID2) {
        CPW(1);                  // KQ(t) ready
        __syncthreads();

        // ---- Phase C: scores + softmax (warp=head, lane=joint) ----
        if (lane < NJ) {
            const char* qb = (const char*)sm2 + O2_Q + (warp * NJ + lane) * 80;
            float q[32];
            h8f(q +  0, *(const uint4*)(qb +  0), SC);
            h8f(q +  8, *(const uint4*)(qb + 16), SC);
            h8f(q + 16, *(const uint4*)(qb + 32), SC);
            h8f(q + 24, *(const uint4*)(qb + 48), SC);
            const float* kp = sm2 + warp * OUTJ;
            float sc[NJ];
#pragma unroll
            for (int m = 0; m < NJ; ++m) {
                const float4* kr = (const float4*)(kp + m * 32);
                float sv = 0.f;
#pragma unroll
                for (int f4 = 0; f4 < 8; ++f4) {
                    float4 kv = kr[f4];
                    sv += q[4*f4+0]*kv.x + q[4*f4+1]*kv.y + q[4*f4+2]*kv.z + q[4*f4+3]*kv.w;
                }
                sc[m] = sv;
            }
            float mx = sc[0];
#pragma unroll
            for (int m = 1; m < NJ; ++m) mx = fmaxf(mx, sc[m]);
            float sum = 0.f;
#pragma unroll
            for (int m = 0; m < NJ; ++m) { sc[m] = __expf(sc[m] - mx); sum += sc[m]; }
            const float inv = 1.f / sum;
            float* ap = att + warp * 576 + lane * 24;
#pragma unroll
            for (int mq = 0; mq < 6; ++mq)
                *(float4*)&ap[mq * 4] = make_float4(sc[4*mq]*inv, sc[4*mq+1]*inv,
                                                   sc[4*mq+2]*inv, sc[4*mq+3]*inv);
        }
        __syncthreads();         // att visible; K/Q free

        const int tn = t + GRID2;
        if (tn < T_TOK) {        // prefetch KQ(t+1) — overlaps phase E
            const float*  Kg = g_K  + (size_t)tn * JD;
            const __half* Qg = g_Qh + (size_t)tn * JD;
#pragma unroll
            for (int it = 0; it < 6; ++it) {
                int i = tid + 256 * it;
                cp16(sb + O2_K + (uint32_t)i * 16, Kg + i * 4);
            }
#pragma unroll
            for (int it = 0; it < 3; ++it) {
                int i = tid + 256 * it;
                cp16(sb + O2_Q + (uint32_t)((i >> 2) * 80 + (i & 3) * 16), Qg + i * 8);
            }
        }
        CPC();
        CPW(1);                  // V(t) ready
        __syncthreads();

        // ---- Phase E: AV + residual (thread = channel (h,f)) ----
        float out[NJ];
        {
            const __half* xg = g_xh + (size_t)t * JD + tid;   // fp16 residual
#pragma unroll
            for (int n = 0; n < NJ; ++n) out[n] = __half2float(xg[n * 256]);
        }
        {
            const __half* vp = (const __half*)((const char*)sm2 + O2_V) + warp * OUTJ + lane;
            const float* ap = att + warp * 576;
#pragma unroll
            for (int mq = 0; mq < 6; ++mq) {
                float v0 = __half2float(vp[(4*mq+0) * 32]);
                float v1 = __half2float(vp[(4*mq+1) * 32]);
                float v2 = __half2float(vp[(4*mq+2) * 32]);
                float v3 = __half2float(vp[(4*mq+3) * 32]);
#pragma unroll
                for (int n = 0; n < NJ; ++n) {
                    float4 a = *(const float4*)&ap[n * 24 + mq * 4];
                    out[n] += a.x*v0 + a.y*v1 + a.z*v2 + a.w*v3;
                }
            }
        }
        // ---- LN over 6144 ----
        float s1 = 0.f, s2 = 0.f;
#pragma unroll
        for (int n = 0; n < NJ; ++n) { s1 += out[n]; s2 += out[n] * out[n]; }
#pragma unroll
        for (int o = 16; o; o >>= 1) {
            s1 += __shfl_xor_sync(0xffffffffu, s1, o);
            s2 += __shfl_xor_sync(0xffffffffu, s2, o);
        }
        if (lane == 0) { red[warp] = s1; red[8 + warp] = s2; }
        __syncthreads();

        if (tn < T_TOK) {        // prefetch V(t+1) — overlaps epilogue
            const __half* Vg = g_Vh + (size_t)tn * JD;
#pragma unroll
            for (int it = 0; it < 3; ++it) {
                int i = tid + 256 * it;
                cp16(sb + O2_V + (uint32_t)i * 16, Vg + i * 8);
            }
        }
        CPC();

        float S1 = 0.f, S2 = 0.f;
#pragma unroll
        for (int w = 0; w < 8; ++w) { S1 += red[w]; S2 += red[8 + w]; }
        const float mu = S1 * (1.0f / JD);
        const float var = S2 * (1.0f / JD) - mu * mu;
        const float rstd = rsqrtf(var + 1e-5f);
        {
            float* yt = y + (size_t)t * JD + tid;
            const float* gp = gamma + tid;
            const float* bp = beta + tid;
#pragma unroll
            for (int n = 0; n < NJ; ++n)
                yt[n * 256] = (out[n] - mu) * rstd * gp[n * 256] + bp[n * 256];
        }
    }
}

// ---------------------------------------------------------------------------
extern "C" void kernel_launch(void* const* d_in, const int* in_sizes, int n_in,
                              void* d_out, int out_size) {
    const float* x     = (const float*)d_in[0];
    const float* Wq    = (const float*)d_in[1];
    const float* bq    = (const float*)d_in[2];
    const float* Wk    = (const float*)d_in[3];
    const float* bk    = (const float*)d_in[4];
    const float* Wv    = (const float*)d_in[5];
    const float* bv    = (const float*)d_in[6];
    const float* gamma = (const float*)d_in[7];
    const float* beta  = (const float*)d_in[8];
    float* y = (float*)d_out;

    cudaFuncSetAttribute(qkv_gemm10_kernel, cudaFuncAttributeMaxDynamicSharedMemorySize, SMEM1);
    cudaFuncSetAttribute(attn_ln10_kernel,  cudaFuncAttributeMaxDynamicSharedMemorySize, SMEM2);

    prep_x_kernel<<<24576, 256>>>(x);
    prep_w_kernel<<<4608, 256>>>(Wq, Wk, Wv);
    prep_b_kernel<<<72, 256>>>(bq, bk, bv);
    qkv_gemm10_kernel<<<288, 256, SMEM1>>>();
    attn_ln10_kernel<<<GRID2, 256, SMEM2>>>(gamma, beta, y);
}